// round 16
// baseline (speedup 1.0000x reference)
#include <cuda_runtime.h>
#include <cuda_fp16.h>
#include <cstdint>

// ---------------- problem constants ----------------
#define BATCH  16384
#define NFEAT  16
#define MTOT   4844
#define KPAD   4864          // pad monomial = 1, pad W = 0
#define KSTAGE 64
#define NSTAGE 76
#define OUTD   256
#define BM     64            // grid 256, 2 CTAs/SM
#define NTHR   256           // 8 warps: 2 (M32) x 4 (N64)
#define EHSTR  162           // fp16 E row stride in halves

// SMEM (bytes): XOR-swizzled 128B rows; A 3-deep, B 2-deep
#define A_BUFSZ 8192                           // 64 x 128B
#define B_BUFSZ 32768                          // 256 x 128B
#define A_OFF   0                              // 3 bufs -> 24576
#define B_OFF   (3 * A_BUFSZ)                  // 24576, 2 bufs -> +65536
#define E_OFF   (B_OFF + 2 * B_BUFSZ)          // 90112, Eh: 64*162*2 = 20736
#define BIAS_OFF (E_OFF + BM * EHSTR * 2)      // 110848
#define SMEM_REQ (BIAS_OFF + OUTD * 4)         // 111872 (x2 CTAs = 223744, fits)

// ---------------- device globals ----------------
__device__ __align__(16) __half   g_Wh[OUTD * KPAD];
__device__ __align__(16) uint32_t g_TBL[KPAD];
__device__ uint32_t g_PAIRT[136];

__device__ __forceinline__ int pair_rank(int a, int b) {
    return a * 16 - (a * (a - 1)) / 2 + (b - a);
}

__global__ void prep_all(const float* __restrict__ W) {
    int idx = blockIdx.x * blockDim.x + threadIdx.x;
    if (idx < 136) {
        int r = idx, a = 0;
        while (r >= 16 - a) { r -= 16 - a; a++; }
        g_PAIRT[idx] = (uint32_t)a | ((uint32_t)(a + r) << 8);
    }
    if (idx < KPAD) {
        int m = idx;
        uint32_t e1 = 0, e2 = 0;
        if (m < 16) {
            e1 = 1 + m; e2 = 0;
        } else if (m < 152) {
            e1 = 17 + (m - 16); e2 = 0;
        } else if (m < 968) {
            int r = m - 152, a = 0;
            while (true) { int k = 16 - a; int t2 = k * (k + 1) / 2; if (r < t2) break; r -= t2; a++; }
            int b = a;
            while (r >= 16 - b) { r -= 16 - b; b++; }
            int c = b + r;
            e1 = 1 + a; e2 = 17 + pair_rank(b, c);
        } else if (m < MTOT) {
            int r = m - 968, a = 0;
            while (true) { int k = 16 - a; int t3 = k * (k + 1) * (k + 2) / 6; if (r < t3) break; r -= t3; a++; }
            int b = a;
            while (true) { int k = 16 - b; int t2 = k * (k + 1) / 2; if (r < t2) break; r -= t2; b++; }
            int c = b;
            while (r >= 16 - c) { r -= 16 - c; c++; }
            int d = c + r;
            e1 = 17 + pair_rank(a, b); e2 = 17 + pair_rank(c, d);
        } else {
            e1 = 0; e2 = 0;
        }
        g_TBL[m] = e1 | (e2 << 16);
    }
    if (idx < OUTD * KPAD) {
        int n = idx / KPAD, k = idx - n * KPAD;
        float w = (k < MTOT) ? W[(size_t)n * MTOT + k] : 0.0f;
        g_Wh[idx] = __float2half_rn(w);
    }
}

// ---------------- PTX helpers ----------------
__device__ __forceinline__ uint32_t smem_u32(const void* p) {
    uint32_t a;
    asm("{ .reg .u64 t; cvta.to.shared.u64 t, %1; cvt.u32.u64 %0, t; }" : "=r"(a) : "l"(p));
    return a;
}
__device__ __forceinline__ void cp_async16(uint32_t dst, const void* src) {
    asm volatile("cp.async.cg.shared.global [%0], [%1], 16;" :: "r"(dst), "l"(src) : "memory");
}
__device__ __forceinline__ void ldsm_x4(uint32_t (&r)[4], uint32_t addr) {
    asm volatile("ldmatrix.sync.aligned.m8n8.x4.shared.b16 {%0,%1,%2,%3}, [%4];"
                 : "=r"(r[0]), "=r"(r[1]), "=r"(r[2]), "=r"(r[3]) : "r"(addr));
}
__device__ __forceinline__ void mma16816(float (&c)[4], const uint32_t (&a)[4],
                                         uint32_t b0, uint32_t b1) {
    asm volatile(
        "mma.sync.aligned.m16n8k16.row.col.f32.f16.f16.f32 "
        "{%0,%1,%2,%3}, {%4,%5,%6,%7}, {%8,%9}, {%0,%1,%2,%3};"
        : "+f"(c[0]), "+f"(c[1]), "+f"(c[2]), "+f"(c[3])
        : "r"(a[0]), "r"(a[1]), "r"(a[2]), "r"(a[3]), "r"(b0), "r"(b1));
}

// ---------------- main fused kernel ----------------
// R15 base; kf=0 mma issued BEFORE the stage's prefetch so the tensor pipe
// is warm while LOAD_B/GEN_A issue in its shadow.
__global__ void __launch_bounds__(NTHR, 2) taylor_main(
    const float* __restrict__ x,
    const float* __restrict__ bias,
    float* __restrict__ out)
{
    extern __shared__ char smem[];
    const uint32_t sbase = smem_u32(smem);
    __half* Eh = (__half*)(smem + E_OFF);
    float* Bias = (float*)(smem + BIAS_OFF);

    const int tid  = threadIdx.x;
    const int wid  = tid >> 5;
    const int lane = tid & 31;
    const int b0   = blockIdx.x * BM;
    const int wm   = wid & 1;
    const int wn   = wid >> 1;

    // ---- prologue: tanh -> fp16 E; bias -> smem ----
    {
        float* Tf = (float*)(smem + A_OFF);
        #pragma unroll
        for (int i = 0; i < (BM * NFEAT) / NTHR; ++i) {
            int q = tid + i * NTHR;
            int row = q >> 4, f = q & 15;
            float t = tanhf(x[(size_t)(b0 + row) * NFEAT + f]);
            Tf[row * 17 + f] = t;
            Eh[row * EHSTR + 1 + f] = __float2half_rn(t);
        }
        if (tid < BM) Eh[tid * EHSTR] = __float2half_rn(1.0f);
        Bias[tid] = __ldg(&bias[tid]);        // 256 threads = 256 cols
        __syncthreads();
        #pragma unroll
        for (int i = 0; i < (136 * BM) / NTHR; ++i) {
            int q = tid + i * NTHR;
            int row = q & 63, p = q >> 6;
            uint32_t pr = g_PAIRT[p];
            Eh[row * EHSTR + 17 + p] = __float2half_rn(
                Tf[row * 17 + (pr & 255)] * Tf[row * 17 + ((pr >> 8) & 255)]);
        }
        __syncthreads();
    }

    // ---- gen assignment ----
    const int grow = tid & 63;
    const int gkb  = (tid >> 6) << 4;
    const int gseg = gkb >> 3;
    const int grb  = grow & 7;
    const __half* Er = Eh + grow * EHSTR;
    const uint32_t gA0 = sbase + A_OFF + grow * 128 + (uint32_t)((gseg    ) ^ grb) * 16;
    const uint32_t gA1 = sbase + A_OFF + grow * 128 + (uint32_t)((gseg + 1) ^ grb) * 16;

    #define GEN_A(s_, bo_) do {                                                     \
        const int mb = (s_) * KSTAGE + gkb;                                         \
        uint32_t tt[16];                                                            \
        *(uint4*)&tt[0]  = *(const uint4*)&g_TBL[mb];                               \
        *(uint4*)&tt[4]  = *(const uint4*)&g_TBL[mb + 4];                           \
        *(uint4*)&tt[8]  = *(const uint4*)&g_TBL[mb + 8];                           \
        *(uint4*)&tt[12] = *(const uint4*)&g_TBL[mb + 12];                          \
        uint32_t hh[8];                                                             \
        _Pragma("unroll")                                                           \
        for (int q = 0; q < 8; ++q) {                                               \
            uint32_t t0 = tt[2 * q], t1 = tt[2 * q + 1];                            \
            __half p0 = __hmul(Er[t0 & 0xffff], Er[t0 >> 16]);                      \
            __half p1 = __hmul(Er[t1 & 0xffff], Er[t1 >> 16]);                      \
            hh[q] = (uint32_t)__half_as_ushort(p0) |                                \
                    ((uint32_t)__half_as_ushort(p1) << 16);                         \
        }                                                                           \
        asm volatile("st.shared.v4.b32 [%0], {%1,%2,%3,%4};"                        \
                     :: "r"(gA0 + (bo_)), "r"(hh[0]), "r"(hh[1]), "r"(hh[2]), "r"(hh[3]) : "memory"); \
        asm volatile("st.shared.v4.b32 [%0], {%1,%2,%3,%4};"                        \
                     :: "r"(gA1 + (bo_)), "r"(hh[4]), "r"(hh[5]), "r"(hh[6]), "r"(hh[7]) : "memory"); \
    } while (0)

    #define LOAD_B(s_, bo_) do {                                                    \
        _Pragma("unroll")                                                           \
        for (int i = 0; i < 8; ++i) {                                               \
            int c = tid + i * NTHR;                                                 \
            int row = c >> 3, seg = c & 7;                                          \
            const __half* src = g_Wh + (size_t)row * KPAD + (s_) * KSTAGE + seg * 8;\
            cp_async16(sbase + B_OFF + (bo_) + row * 128 +                          \
                       (uint32_t)(seg ^ (row & 7)) * 16, src);                      \
        }                                                                           \
        asm volatile("cp.async.commit_group;" ::: "memory");                        \
    } while (0)

    // ---- pipeline prologue ----
    GEN_A(0, 0);
    GEN_A(1, A_BUFSZ);
    LOAD_B(0, 0);

    float acc[2][8][4];
    #pragma unroll
    for (int i = 0; i < 2; ++i)
        #pragma unroll
        for (int j = 0; j < 8; ++j)
            #pragma unroll
            for (int q = 0; q < 4; ++q) acc[i][j][q] = 0.0f;

    const int ra   = wm * 32 + (lane & 15);
    const int arb  = ra & 7;
    const int alog = lane >> 4;
    const uint32_t aBase = sbase + A_OFF + ra * 128;

    const int bq    = lane >> 3;
    const int rbrow = wn * 64 + ((bq >> 1) << 3) + (lane & 7);
    const int brb   = rbrow & 7;
    const int blog  = bq & 1;
    const uint32_t bBase = sbase + B_OFF + rbrow * 128;

    int bufA = 0, bufA2 = 2 * A_BUFSZ;

    // one kf's worth of mma, as a macro over frag locals
    #define DO_KF(kf_) do {                                                          \
        uint32_t a[2][4];                                                            \
        const uint32_t aoff = (uint32_t)((alog + 2 * (kf_)) ^ arb) * 16;             \
        ldsm_x4(a[0], aB + aoff);                                                    \
        ldsm_x4(a[1], aB + aoff + 16 * 128);                                         \
        const uint32_t boff = (uint32_t)((blog + 2 * (kf_)) ^ brb) * 16;             \
        _Pragma("unroll")                                                            \
        for (int nb = 0; nb < 4; ++nb) {                                             \
            uint32_t b[4];                                                           \
            ldsm_x4(b, bB + nb * (16 * 128) + boff);                                 \
            mma16816(acc[0][nb * 2 + 0], a[0], b[0], b[1]);                          \
            mma16816(acc[0][nb * 2 + 1], a[0], b[2], b[3]);                          \
            mma16816(acc[1][nb * 2 + 0], a[1], b[0], b[1]);                          \
            mma16816(acc[1][nb * 2 + 1], a[1], b[2], b[3]);                          \
        }                                                                            \
    } while (0)

    // ---- main loop: ONE barrier per stage; kf=0 mma BEFORE prefetch ----
    for (int s = 0; s < NSTAGE; ++s) {
        asm volatile("cp.async.wait_group 0;" ::: "memory");   // B(s) landed
        __syncthreads();   // A(s)/B(s) visible; stage s-1 fully consumed

        const uint32_t aB = aBase + bufA;
        const uint32_t bB = bBase + (s & 1) * B_BUFSZ;

        DO_KF(0);                                        // warm the tensor pipe

        if (s + 1 < NSTAGE) LOAD_B(s + 1, ((s + 1) & 1) * B_BUFSZ);
        if (s + 2 < NSTAGE) GEN_A(s + 2, bufA2);         // issues in mma shadow

        DO_KF(1);
        DO_KF(2);
        DO_KF(3);

        bufA += A_BUFSZ;  if (bufA  == 3 * A_BUFSZ) bufA  = 0;
        bufA2 += A_BUFSZ; if (bufA2 == 3 * A_BUFSZ) bufA2 = 0;
    }

    // ---- epilogue: bias + relu + store ----
    {
        const int rbase = b0 + wm * 32 + (lane >> 2);
        const int cbase = wn * 64 + (lane & 3) * 2;
        #pragma unroll
        for (int mf = 0; mf < 2; ++mf) {
            #pragma unroll
            for (int nf = 0; nf < 8; ++nf) {
                const int col = cbase + nf * 8;
                const float bz0 = Bias[col], bz1 = Bias[col + 1];
                const int r0 = rbase + mf * 16;
                float2 v0, v1;
                v0.x = fmaxf(acc[mf][nf][0] + bz0, 0.0f);
                v0.y = fmaxf(acc[mf][nf][1] + bz1, 0.0f);
                v1.x = fmaxf(acc[mf][nf][2] + bz0, 0.0f);
                v1.y = fmaxf(acc[mf][nf][3] + bz1, 0.0f);
                *reinterpret_cast<float2*>(out + (size_t)r0 * OUTD + col)       = v0;
                *reinterpret_cast<float2*>(out + (size_t)(r0 + 8) * OUTD + col) = v1;
            }
        }
    }
    #undef GEN_A
    #undef LOAD_B
    #undef DO_KF
}

// ---------------- launch ----------------
extern "C" void kernel_launch(void* const* d_in, const int* in_sizes, int n_in,
                              void* d_out, int out_size) {
    const float* x = (const float*)d_in[0];
    const float* W = (const float*)d_in[1];
    const float* b = (const float*)d_in[2];
    float* out = (float*)d_out;

    cudaFuncSetAttribute(taylor_main, cudaFuncAttributeMaxDynamicSharedMemorySize, SMEM_REQ);

    prep_all<<<(OUTD * KPAD + 255) / 256, 256>>>(W);
    taylor_main<<<BATCH / BM, NTHR, SMEM_REQ>>>(x, b, out);
}